// round 5
// baseline (speedup 1.0000x reference)
#include <cuda_runtime.h>
#include <cuda_bf16.h>
#include <math_constants.h>
#include <cstdint>

// Problem constants
#define B_    2
#define T_    2048
#define C_    1024
#define H_    16
#define D_    64
#define M_    (B_ * T_)      // 4096
#define QKVN  (3 * C_)       // 3072
#define K_    1024

// ---------------------------------------------------------------------------
// Device scratch
// ---------------------------------------------------------------------------
__device__ __nv_bfloat16 s_xh[(size_t)M_ * C_];
__device__ __nv_bfloat16 s_xl[(size_t)M_ * C_];
__device__ __nv_bfloat16 s_wqh[(size_t)QKVN * C_];
__device__ __nv_bfloat16 s_wql[(size_t)QKVN * C_];
__device__ __nv_bfloat16 s_qkvh[(size_t)M_ * QKVN];   // q|k used, v third unused
__device__ __nv_bfloat16 s_qkvl[(size_t)M_ * QKVN];
__device__ __nv_bfloat16 s_vth[(size_t)B_ * H_ * D_ * T_];  // V transposed
__device__ __nv_bfloat16 s_vtl[(size_t)B_ * H_ * D_ * T_];
__device__ __nv_bfloat16 s_ah[(size_t)M_ * C_];
__device__ __nv_bfloat16 s_al[(size_t)M_ * C_];
__device__ __nv_bfloat16 s_wph[(size_t)C_ * C_];
__device__ __nv_bfloat16 s_wpl[(size_t)C_ * C_];

// ---------------------------------------------------------------------------
// PTX helpers
// ---------------------------------------------------------------------------
__device__ __forceinline__ uint32_t smem_u32(const void* p) {
    uint32_t a;
    asm("{ .reg .u64 t; cvta.to.shared.u64 t, %1; cvt.u32.u64 %0, t; }"
        : "=r"(a) : "l"(p));
    return a;
}

#define CP_ASYNC_16(dst, src) \
    asm volatile("cp.async.cg.shared.global [%0], [%1], 16;" \
                 :: "r"(dst), "l"(src) : "memory")
#define CP_ASYNC_COMMIT() asm volatile("cp.async.commit_group;" ::: "memory")
#define CP_ASYNC_WAIT_1() asm volatile("cp.async.wait_group 1;" ::: "memory")
#define CP_ASYNC_WAIT_0() asm volatile("cp.async.wait_group 0;" ::: "memory")

__device__ __forceinline__ void ldm_x4(uint32_t& r0, uint32_t& r1,
                                       uint32_t& r2, uint32_t& r3, uint32_t a) {
    asm volatile("ldmatrix.sync.aligned.m8n8.x4.shared.b16 {%0,%1,%2,%3}, [%4];"
                 : "=r"(r0), "=r"(r1), "=r"(r2), "=r"(r3) : "r"(a));
}

__device__ __forceinline__ void mma16816(float* c, const uint32_t* a,
                                         const uint32_t* b) {
    asm volatile(
        "mma.sync.aligned.m16n8k16.row.col.f32.bf16.bf16.f32 "
        "{%0,%1,%2,%3}, {%4,%5,%6,%7}, {%8,%9}, {%0,%1,%2,%3};"
        : "+f"(c[0]), "+f"(c[1]), "+f"(c[2]), "+f"(c[3])
        : "r"(a[0]), "r"(a[1]), "r"(a[2]), "r"(a[3]), "r"(b[0]), "r"(b[1]));
}

__device__ __forceinline__ void split2(float f0, float f1,
                                       uint32_t& hi, uint32_t& lo) {
    __nv_bfloat16 h0 = __float2bfloat16_rn(f0);
    __nv_bfloat16 h1 = __float2bfloat16_rn(f1);
    float l0 = f0 - __bfloat162float(h0);
    float l1 = f1 - __bfloat162float(h1);
    __nv_bfloat162 th; th.x = h0; th.y = h1;
    __nv_bfloat162 tl; tl.x = __float2bfloat16_rn(l0); tl.y = __float2bfloat16_rn(l1);
    hi = *(uint32_t*)&th;
    lo = *(uint32_t*)&tl;
}

__device__ __forceinline__ void split1(float f, __nv_bfloat16& h, __nv_bfloat16& l) {
    h = __float2bfloat16_rn(f);
    l = __float2bfloat16_rn(f - __bfloat162float(h));
}

// fast exp2 on FMA pipe (error ~2.4e-6)
__device__ __forceinline__ float fexp2(float x) {
    x = fmaxf(x, -120.f);
    int ni = __float2int_rn(x);
    float f = x - (float)ni;
    float p =          1.3333558146e-3f;
    p = fmaf(p, f, 9.6181291076e-3f);
    p = fmaf(p, f, 5.5504108664e-2f);
    p = fmaf(p, f, 2.4022650696e-1f);
    p = fmaf(p, f, 6.9314718056e-1f);
    p = fmaf(p, f, 1.0f);
    return __int_as_float((ni + 127) << 23) * p;
}

// ---------------------------------------------------------------------------
// bf16 hi/lo split of an fp32 buffer
// ---------------------------------------------------------------------------
__global__ __launch_bounds__(256)
void split_bf16_kernel(const float* __restrict__ in,
                       __nv_bfloat16* __restrict__ hi,
                       __nv_bfloat16* __restrict__ lo, int n2)
{
    int i = blockIdx.x * blockDim.x + threadIdx.x;
    if (i >= n2) return;
    float2 v = ((const float2*)in)[i];
    uint32_t h, l;
    split2(v.x, v.y, h, l);
    ((uint32_t*)hi)[i] = h;
    ((uint32_t*)lo)[i] = l;
}

// ---------------------------------------------------------------------------
// mma.sync bf16 split-GEMM, 3 passes (hh, lh, hl).
// CTA: 128 thr = 4 warps (2x2), CTA tile 128x128, warp tile 64x64, BK=64.
// SPLIT_OUT: write bf16 hi/lo; V block (n >= 2C) written TRANSPOSED to vth/vtl.
// ---------------------------------------------------------------------------
#define KT_   (K_ / 64)
#define NIT_  (3 * KT_)
#define TILEB 16384
#define GEMM_SMEM (4 * TILEB + 128)

__device__ __forceinline__ void issue_tile_load(
    int L,
    const __nv_bfloat16* __restrict__ Ah, const __nv_bfloat16* __restrict__ Al,
    const __nv_bfloat16* __restrict__ Bh, const __nv_bfloat16* __restrict__ Bl,
    uint32_t sA, uint32_t sB, int m0, int n0, int tid)
{
    const int p  = L >> 4;
    const int kt = L & 15;
    const __nv_bfloat16* A = (p == 1) ? Al : Ah;
    const __nv_bfloat16* B = (p == 2) ? Bl : Bh;
    const int row = tid;                 // 0..127
    const uint32_t rb = (uint32_t)row * 128u;
    const uint32_t rx = ((uint32_t)row & 7u) << 4;
    const __nv_bfloat16* ga = A + (size_t)(m0 + row) * K_ + kt * 64;
    const __nv_bfloat16* gb = B + (size_t)(n0 + row) * K_ + kt * 64;
#pragma unroll
    for (int c = 0; c < 8; c++) {
        const uint32_t sw = rb + (((uint32_t)c * 16u) ^ rx);
        CP_ASYNC_16(sA + sw, ga + c * 8);
        CP_ASYNC_16(sB + sw, gb + c * 8);
    }
    CP_ASYNC_COMMIT();
}

template<bool SPLIT_OUT>
__global__ __launch_bounds__(128, 2)
void gemm_bf16_split_kernel(const __nv_bfloat16* __restrict__ Ah,
                            const __nv_bfloat16* __restrict__ Al,
                            const __nv_bfloat16* __restrict__ Bh,
                            const __nv_bfloat16* __restrict__ Bl,
                            float* __restrict__ Cm,
                            __nv_bfloat16* __restrict__ Oh,
                            __nv_bfloat16* __restrict__ Ol,
                            __nv_bfloat16* __restrict__ Vth,
                            __nv_bfloat16* __restrict__ Vtl, int N)
{
    extern __shared__ char dsm[];
    const uint32_t base = (smem_u32(dsm) + 127u) & ~127u;

    const int tid  = threadIdx.x;
    const int wid  = tid >> 5;
    const int lane = tid & 31;
    const int wm   = wid >> 1;          // 0..1
    const int wn   = wid & 1;           // 0..1
    const int m0 = blockIdx.y * 128;
    const int n0 = blockIdx.x * 128;

    const uint32_t sA[2] = { base,         base + 2 * TILEB };
    const uint32_t sB[2] = { base + TILEB, base + 3 * TILEB };

    float acc[4][8][4];
#pragma unroll
    for (int i = 0; i < 4; i++)
#pragma unroll
        for (int j = 0; j < 8; j++)
#pragma unroll
            for (int q = 0; q < 4; q++) acc[i][j][q] = 0.f;

    const int lr = lane & 15;
    const uint32_t lc = ((uint32_t)(lane >> 4)) << 4;

    issue_tile_load(0, Ah, Al, Bh, Bl, sA[0], sB[0], m0, n0, tid);
    issue_tile_load(1, Ah, Al, Bh, Bl, sA[1], sB[1], m0, n0, tid);

    for (int it = 0; it < NIT_; ++it) {
        const int s = it & 1;
        if (it + 2 < NIT_) { CP_ASYNC_WAIT_1(); } else { CP_ASYNC_WAIT_0(); }
        __syncthreads();

#pragma unroll
        for (int kk = 0; kk < 4; kk++) {
            const uint32_t colb = (uint32_t)kk * 32u + lc;
            uint32_t a[4][4];
#pragma unroll
            for (int mi = 0; mi < 4; mi++) {
                const int row = wm * 64 + mi * 16 + lr;
                const uint32_t ad = sA[s] + (uint32_t)row * 128u +
                                    (colb ^ (((uint32_t)row & 7u) << 4));
                ldm_x4(a[mi][0], a[mi][1], a[mi][2], a[mi][3], ad);
            }
            uint32_t b[8][2];
#pragma unroll
            for (int bj = 0; bj < 4; bj++) {
                const int row = wn * 64 + bj * 16 + lr;
                const uint32_t ad = sB[s] + (uint32_t)row * 128u +
                                    (colb ^ (((uint32_t)row & 7u) << 4));
                uint32_t r0, r1, r2, r3;
                ldm_x4(r0, r1, r2, r3, ad);
                b[bj * 2 + 0][0] = r0; b[bj * 2 + 1][0] = r1;
                b[bj * 2 + 0][1] = r2; b[bj * 2 + 1][1] = r3;
            }
#pragma unroll
            for (int mi = 0; mi < 4; mi++)
#pragma unroll
                for (int ni = 0; ni < 8; ni++)
                    mma16816(acc[mi][ni], a[mi], b[ni]);
        }
        __syncthreads();

        if (it + 2 < NIT_)
            issue_tile_load(it + 2, Ah, Al, Bh, Bl, sA[s], sB[s], m0, n0, tid);
    }

    const int rr = lane >> 2;
    const int cc = (lane & 3) * 2;
    const bool vblock = SPLIT_OUT && (n0 >= 2 * C_);
#pragma unroll
    for (int mi = 0; mi < 4; mi++) {
#pragma unroll
        for (int ni = 0; ni < 8; ni++) {
            const int gm = m0 + wm * 64 + mi * 16 + rr;
            const int gn = n0 + wn * 64 + ni * 8 + cc;
            if (!SPLIT_OUT) {
                *(float2*)(Cm + (size_t)gm * N + gn) =
                    make_float2(acc[mi][ni][0], acc[mi][ni][1]);
                *(float2*)(Cm + (size_t)(gm + 8) * N + gn) =
                    make_float2(acc[mi][ni][2], acc[mi][ni][3]);
            } else if (!vblock) {
                uint32_t h, l;
                split2(acc[mi][ni][0], acc[mi][ni][1], h, l);
                *(uint32_t*)(Oh + (size_t)gm * N + gn) = h;
                *(uint32_t*)(Ol + (size_t)gm * N + gn) = l;
                split2(acc[mi][ni][2], acc[mi][ni][3], h, l);
                *(uint32_t*)(Oh + (size_t)(gm + 8) * N + gn) = h;
                *(uint32_t*)(Ol + (size_t)(gm + 8) * N + gn) = l;
            } else {
                // V block: write transposed Vt[b, h, d, t]
                const int bb = gm >> 11;           // gm / T_
                const int t  = gm & (T_ - 1);
                const int hd = gn - 2 * C_;        // 0..1023
                const size_t ib = ((size_t)(bb * H_ + (hd >> 6)) * D_ + (hd & 63))
                                  * T_ + t;
                __nv_bfloat16 h, l;
                split1(acc[mi][ni][0], h, l); Vth[ib] = h;        Vtl[ib] = l;
                split1(acc[mi][ni][1], h, l); Vth[ib + T_] = h;   Vtl[ib + T_] = l;
                split1(acc[mi][ni][2], h, l); Vth[ib + 8] = h;    Vtl[ib + 8] = l;
                split1(acc[mi][ni][3], h, l); Vth[ib + T_ + 8] = h; Vtl[ib + T_ + 8] = l;
            }
        }
    }
}

// ---------------------------------------------------------------------------
// Tensor-core flash attention (causal), bf16 hi/lo, poly-exp2 softmax.
// V consumed pre-transposed (Vt[b,h,d,t]) -> no in-kernel transpose,
// single __syncthreads per KV tile.
// CTA: 256 thr = 8 warps, BQ=128, BKV=64, D=64.
// ---------------------------------------------------------------------------
#define BQ_   128
#define BKV_  64
#define AQH   0u
#define AQL   16384u
#define AKST  32768u      // + s*16384 : Kh +0, Kl +8192
#define AVST  65536u      // + s*16384 : Vth +0, Vtl +8192
#define ATTN_SMEM (98304 + 1024)

__global__ __launch_bounds__(256, 1)
void attn_mma_kernel(const __nv_bfloat16* __restrict__ qh_g,
                     const __nv_bfloat16* __restrict__ ql_g,
                     const __nv_bfloat16* __restrict__ vth_g,
                     const __nv_bfloat16* __restrict__ vtl_g,
                     __nv_bfloat16* __restrict__ oh_g,
                     __nv_bfloat16* __restrict__ ol_g)
{
    extern __shared__ char dsm[];
    char* sm = (char*)(((uintptr_t)dsm + 1023) & ~(uintptr_t)1023);
    const uint32_t smb = smem_u32(sm);

    const int qb = (int)gridDim.x - 1 - (int)blockIdx.x;  // big work first
    const int h  = blockIdx.y, b = blockIdx.z;
    const int q0 = qb * BQ_;
    const int tid  = threadIdx.x;
    const int w    = tid >> 5;
    const int lane = tid & 31;
    const int lr   = lane & 15;
    const uint32_t lc = ((uint32_t)(lane >> 4)) << 4;
    const float SC = 0.18033688011f;   // (1/8) * log2(e)

    // ---- prologue: Q tile (hi+lo) ----
    {
        const int r  = tid >> 1;
        const int cb = (tid & 1) * 4;
        const size_t grow = (size_t)(b * T_ + q0 + r) * QKVN + h * D_;
#pragma unroll
        for (int c = 0; c < 4; c++) {
            const uint32_t off = (uint32_t)r * 128u +
                (((uint32_t)(cb + c) * 16u) ^ (((uint32_t)r & 7u) << 4));
            CP_ASYNC_16(smb + AQH + off, qh_g + grow + (cb + c) * 8);
            CP_ASYNC_16(smb + AQL + off, ql_g + grow + (cb + c) * 8);
        }
        CP_ASYNC_COMMIT();
    }

    // KV tile loader: K (qkv layout) + Vt (transposed layout), hi+lo
    auto issue_kv = [&](int kt, int s) {
        const int r  = tid >> 2;          // 0..63
        const int c0 = tid & 3;
        const size_t krow = (size_t)(b * T_ + kt * BKV_ + r) * QKVN + C_ + h * D_;
        const size_t vrow = ((size_t)((b * H_ + h) * D_) + r) * T_ + kt * BKV_;
        const uint32_t ks = smb + AKST + (uint32_t)s * 16384u;
        const uint32_t vs = smb + AVST + (uint32_t)s * 16384u;
        const uint32_t rx = ((uint32_t)r & 7u) << 4;
#pragma unroll
        for (int q = 0; q < 2; q++) {
            const int c = c0 + q * 4;
            const uint32_t off = (uint32_t)r * 128u + (((uint32_t)c * 16u) ^ rx);
            CP_ASYNC_16(ks + off,         qh_g  + krow + c * 8);
            CP_ASYNC_16(ks + 8192u + off, ql_g  + krow + c * 8);
            CP_ASYNC_16(vs + off,         vth_g + vrow + c * 8);
            CP_ASYNC_16(vs + 8192u + off, vtl_g + vrow + c * 8);
        }
        CP_ASYNC_COMMIT();
    };

    issue_kv(0, 0);
    CP_ASYNC_WAIT_1();      // Q group done
    __syncthreads();

    // ---- Q fragments into registers ----
    uint32_t qhf[4][4], qlf[4][4];
#pragma unroll
    for (int kk = 0; kk < 4; kk++) {
        const int row = w * 16 + lr;
        const uint32_t colb = (uint32_t)kk * 32u + lc;
        const uint32_t sw = (uint32_t)row * 128u +
                            (colb ^ (((uint32_t)row & 7u) << 4));
        ldm_x4(qhf[kk][0], qhf[kk][1], qhf[kk][2], qhf[kk][3], smb + AQH + sw);
        ldm_x4(qlf[kk][0], qlf[kk][1], qlf[kk][2], qlf[kk][3], smb + AQL + sw);
    }

    float acco[8][4];
#pragma unroll
    for (int j = 0; j < 8; j++)
#pragma unroll
        for (int q = 0; q < 4; q++) acco[j][q] = 0.f;
    float m_[2] = { -1e30f, -1e30f };
    float l_[2] = { 0.f, 0.f };

    const int nkb = 2 * qb + 2;
    for (int kt = 0; kt < nkb; kt++) {
        const int s  = kt & 1;
        const int k0 = kt * BKV_;
        CP_ASYNC_WAIT_0();
        __syncthreads();                 // single barrier per tile
        if (kt + 1 < nkb) issue_kv(kt + 1, s ^ 1);

        const uint32_t ks = smb + AKST + (uint32_t)s * 16384u;
        const uint32_t vs = smb + AVST + (uint32_t)s * 16384u;

        // ---- S = Q @ K^T (3-pass split) ----
        float accs[8][4];
#pragma unroll
        for (int j = 0; j < 8; j++)
#pragma unroll
            for (int q = 0; q < 4; q++) accs[j][q] = 0.f;

#pragma unroll
        for (int kk = 0; kk < 4; kk++) {
            uint32_t bh[8][2], bl[8][2];
#pragma unroll
            for (int bj = 0; bj < 4; bj++) {
                const int row = bj * 16 + lr;
                const uint32_t colb = (uint32_t)kk * 32u + lc;
                const uint32_t ad = ks + (uint32_t)row * 128u +
                                    (colb ^ (((uint32_t)row & 7u) << 4));
                uint32_t r0, r1, r2, r3;
                ldm_x4(r0, r1, r2, r3, ad);
                bh[bj*2][0]=r0; bh[bj*2+1][0]=r1; bh[bj*2][1]=r2; bh[bj*2+1][1]=r3;
                ldm_x4(r0, r1, r2, r3, ad + 8192u);
                bl[bj*2][0]=r0; bl[bj*2+1][0]=r1; bl[bj*2][1]=r2; bl[bj*2+1][1]=r3;
            }
#pragma unroll
            for (int j = 0; j < 8; j++) {
                mma16816(accs[j], qhf[kk], bh[j]);
                mma16816(accs[j], qlf[kk], bh[j]);
                mma16816(accs[j], qhf[kk], bl[j]);
            }
        }

        // ---- causal mask + online softmax ----
        const int qg_base = q0 + w * 16 + (lane >> 2);
        const bool full = (k0 + BKV_ - 1) <= (q0 + w * 16);  // warp-uniform
#pragma unroll
        for (int pp = 0; pp < 2; pp++) {
            const int qg = qg_base + 8 * pp;
            float mx = m_[pp];
            if (full) {
#pragma unroll
                for (int j = 0; j < 8; j++) {
                    float v0 = accs[j][2*pp  ] * SC;
                    float v1 = accs[j][2*pp+1] * SC;
                    accs[j][2*pp] = v0; accs[j][2*pp+1] = v1;
                    mx = fmaxf(mx, fmaxf(v0, v1));
                }
            } else {
#pragma unroll
                for (int j = 0; j < 8; j++) {
                    const int kg = k0 + j * 8 + (lane & 3) * 2;
                    float v0 = (kg     <= qg) ? accs[j][2*pp  ] * SC : -1e30f;
                    float v1 = (kg + 1 <= qg) ? accs[j][2*pp+1] * SC : -1e30f;
                    accs[j][2*pp] = v0; accs[j][2*pp+1] = v1;
                    mx = fmaxf(mx, fmaxf(v0, v1));
                }
            }
            mx = fmaxf(mx, __shfl_xor_sync(0xffffffffu, mx, 1));
            mx = fmaxf(mx, __shfl_xor_sync(0xffffffffu, mx, 2));
            const float alpha = fexp2(m_[pp] - mx);
            float rs = 0.f;
#pragma unroll
            for (int j = 0; j < 8; j++) {
                const float p0 = fexp2(accs[j][2*pp  ] - mx);
                const float p1 = fexp2(accs[j][2*pp+1] - mx);
                accs[j][2*pp] = p0; accs[j][2*pp+1] = p1;
                rs += p0 + p1;
            }
            rs += __shfl_xor_sync(0xffffffffu, rs, 1);
            rs += __shfl_xor_sync(0xffffffffu, rs, 2);
            l_[pp] = l_[pp] * alpha + rs;
            m_[pp] = mx;
#pragma unroll
            for (int j = 0; j < 8; j++) {
                acco[j][2*pp] *= alpha; acco[j][2*pp+1] *= alpha;
            }
        }

        // ---- pack P (hi/lo) into A fragments ----
        uint32_t ph[4][4], pl[4][4];
#pragma unroll
        for (int t = 0; t < 4; t++) {
            split2(accs[2*t  ][0], accs[2*t  ][1], ph[t][0], pl[t][0]);
            split2(accs[2*t  ][2], accs[2*t  ][3], ph[t][1], pl[t][1]);
            split2(accs[2*t+1][0], accs[2*t+1][1], ph[t][2], pl[t][2]);
            split2(accs[2*t+1][2], accs[2*t+1][3], ph[t][3], pl[t][3]);
        }

        // ---- O += P @ V (3-pass split), B frags straight from Vt smem ----
#pragma unroll
        for (int kk = 0; kk < 4; kk++) {
            uint32_t bvh[8][2], bvl[8][2];
#pragma unroll
            for (int bj = 0; bj < 4; bj++) {
                const int row = bj * 16 + lr;                 // d index
                const uint32_t colb = (uint32_t)kk * 32u + lc; // kv bytes
                const uint32_t sw = (uint32_t)row * 128u +
                                    (colb ^ (((uint32_t)row & 7u) << 4));
                uint32_t r0, r1, r2, r3;
                ldm_x4(r0, r1, r2, r3, vs + sw);
                bvh[bj*2][0]=r0; bvh[bj*2+1][0]=r1; bvh[bj*2][1]=r2; bvh[bj*2+1][1]=r3;
                ldm_x4(r0, r1, r2, r3, vs + 8192u + sw);
                bvl[bj*2][0]=r0; bvl[bj*2+1][0]=r1; bvl[bj*2][1]=r2; bvl[bj*2+1][1]=r3;
            }
#pragma unroll
            for (int j = 0; j < 8; j++) {
                mma16816(acco[j], ph[kk], bvh[j]);
                mma16816(acco[j], pl[kk], bvh[j]);
                mma16816(acco[j], ph[kk], bvl[j]);
            }
        }
    }

    // ---- epilogue ----
#pragma unroll
    for (int pp = 0; pp < 2; pp++) {
        const float inv = 1.f / l_[pp];
        const size_t row = (size_t)(b * T_ + q0 + w * 16 + (lane >> 2) + 8 * pp);
#pragma unroll
        for (int j = 0; j < 8; j++) {
            const int dcol = h * D_ + j * 8 + (lane & 3) * 2;
            uint32_t hbits, lbits;
            split2(acco[j][2*pp] * inv, acco[j][2*pp+1] * inv, hbits, lbits);
            *(uint32_t*)(oh_g + row * C_ + dcol) = hbits;
            *(uint32_t*)(ol_g + row * C_ + dcol) = lbits;
        }
    }
}

// ---------------------------------------------------------------------------
extern "C" void kernel_launch(void* const* d_in, const int* in_sizes, int n_in,
                              void* d_out, int out_size)
{
    (void)in_sizes; (void)n_in; (void)out_size;
    const float* x     = (const float*)d_in[0];
    const float* wqkv  = (const float*)d_in[1];
    const float* wproj = (const float*)d_in[2];
    float* out = (float*)d_out;

    __nv_bfloat16 *xh, *xl, *wqh, *wql, *qkvh, *qkvl, *vth, *vtl, *ah, *al, *wph, *wpl;
    cudaGetSymbolAddress((void**)&xh,   s_xh);
    cudaGetSymbolAddress((void**)&xl,   s_xl);
    cudaGetSymbolAddress((void**)&wqh,  s_wqh);
    cudaGetSymbolAddress((void**)&wql,  s_wql);
    cudaGetSymbolAddress((void**)&qkvh, s_qkvh);
    cudaGetSymbolAddress((void**)&qkvl, s_qkvl);
    cudaGetSymbolAddress((void**)&vth,  s_vth);
    cudaGetSymbolAddress((void**)&vtl,  s_vtl);
    cudaGetSymbolAddress((void**)&ah,   s_ah);
    cudaGetSymbolAddress((void**)&al,   s_al);
    cudaGetSymbolAddress((void**)&wph,  s_wph);
    cudaGetSymbolAddress((void**)&wpl,  s_wpl);

    cudaFuncSetAttribute(gemm_bf16_split_kernel<true>,
                         cudaFuncAttributeMaxDynamicSharedMemorySize, GEMM_SMEM);
    cudaFuncSetAttribute(gemm_bf16_split_kernel<false>,
                         cudaFuncAttributeMaxDynamicSharedMemorySize, GEMM_SMEM);
    cudaFuncSetAttribute(attn_mma_kernel,
                         cudaFuncAttributeMaxDynamicSharedMemorySize, ATTN_SMEM);

    // 1) split inputs
    {
        int n2 = (M_ * C_) / 2;
        split_bf16_kernel<<<(n2 + 255) / 256, 256>>>(x, xh, xl, n2);
        int w2 = (QKVN * C_) / 2;
        split_bf16_kernel<<<(w2 + 255) / 256, 256>>>(wqkv, wqh, wql, w2);
        int p2 = (C_ * C_) / 2;
        split_bf16_kernel<<<(p2 + 255) / 256, 256>>>(wproj, wph, wpl, p2);
    }
    // 2) QKV projection -> q,k packed hi/lo; V transposed hi/lo
    gemm_bf16_split_kernel<true><<<dim3(QKVN / 128, M_ / 128), 128, GEMM_SMEM>>>(
        xh, xl, wqh, wql, nullptr, qkvh, qkvl, vth, vtl, QKVN);
    // 3) causal flash attention (tensor cores)
    attn_mma_kernel<<<dim3(T_ / BQ_, H_, B_), 256, ATTN_SMEM>>>(
        qkvh, qkvl, vth, vtl, ah, al);
    // 4) output projection -> fp32
    gemm_bf16_split_kernel<false><<<dim3(C_ / 128, M_ / 128), 128, GEMM_SMEM>>>(
        ah, al, wph, wpl, out, nullptr, nullptr, nullptr, nullptr, C_);
}

// round 6
// speedup vs baseline: 1.5391x; 1.5391x over previous
#include <cuda_runtime.h>
#include <cuda_bf16.h>
#include <math_constants.h>
#include <cstdint>

// Problem constants
#define B_    2
#define T_    2048
#define C_    1024
#define H_    16
#define D_    64
#define M_    (B_ * T_)      // 4096
#define QKVN  (3 * C_)       // 3072
#define K_    1024

// ---------------------------------------------------------------------------
// Device scratch
// ---------------------------------------------------------------------------
__device__ __nv_bfloat16 s_xh[(size_t)M_ * C_];
__device__ __nv_bfloat16 s_xl[(size_t)M_ * C_];
__device__ __nv_bfloat16 s_wqh[(size_t)QKVN * C_];
__device__ __nv_bfloat16 s_wql[(size_t)QKVN * C_];
__device__ __nv_bfloat16 s_qkvh[(size_t)M_ * QKVN];
__device__ __nv_bfloat16 s_qkvl[(size_t)M_ * QKVN];
__device__ __nv_bfloat16 s_ah[(size_t)M_ * C_];
__device__ __nv_bfloat16 s_al[(size_t)M_ * C_];
__device__ __nv_bfloat16 s_wph[(size_t)C_ * C_];
__device__ __nv_bfloat16 s_wpl[(size_t)C_ * C_];

// ---------------------------------------------------------------------------
// PTX helpers
// ---------------------------------------------------------------------------
__device__ __forceinline__ uint32_t smem_u32(const void* p) {
    uint32_t a;
    asm("{ .reg .u64 t; cvta.to.shared.u64 t, %1; cvt.u32.u64 %0, t; }"
        : "=r"(a) : "l"(p));
    return a;
}

#define CP_ASYNC_16(dst, src) \
    asm volatile("cp.async.cg.shared.global [%0], [%1], 16;" \
                 :: "r"(dst), "l"(src) : "memory")
#define CP_ASYNC_COMMIT() asm volatile("cp.async.commit_group;" ::: "memory")
#define CP_ASYNC_WAIT_1() asm volatile("cp.async.wait_group 1;" ::: "memory")
#define CP_ASYNC_WAIT_0() asm volatile("cp.async.wait_group 0;" ::: "memory")

__device__ __forceinline__ void ldm_x4(uint32_t& r0, uint32_t& r1,
                                       uint32_t& r2, uint32_t& r3, uint32_t a) {
    asm volatile("ldmatrix.sync.aligned.m8n8.x4.shared.b16 {%0,%1,%2,%3}, [%4];"
                 : "=r"(r0), "=r"(r1), "=r"(r2), "=r"(r3) : "r"(a));
}

__device__ __forceinline__ void ldm_x4_trans(uint32_t& r0, uint32_t& r1,
                                             uint32_t& r2, uint32_t& r3, uint32_t a) {
    asm volatile("ldmatrix.sync.aligned.m8n8.x4.trans.shared.b16 {%0,%1,%2,%3}, [%4];"
                 : "=r"(r0), "=r"(r1), "=r"(r2), "=r"(r3) : "r"(a));
}

__device__ __forceinline__ void mma16816(float* c, const uint32_t* a,
                                         const uint32_t* b) {
    asm volatile(
        "mma.sync.aligned.m16n8k16.row.col.f32.bf16.bf16.f32 "
        "{%0,%1,%2,%3}, {%4,%5,%6,%7}, {%8,%9}, {%0,%1,%2,%3};"
        : "+f"(c[0]), "+f"(c[1]), "+f"(c[2]), "+f"(c[3])
        : "r"(a[0]), "r"(a[1]), "r"(a[2]), "r"(a[3]), "r"(b[0]), "r"(b[1]));
}

__device__ __forceinline__ void split2(float f0, float f1,
                                       uint32_t& hi, uint32_t& lo) {
    __nv_bfloat16 h0 = __float2bfloat16_rn(f0);
    __nv_bfloat16 h1 = __float2bfloat16_rn(f1);
    float l0 = f0 - __bfloat162float(h0);
    float l1 = f1 - __bfloat162float(h1);
    __nv_bfloat162 th; th.x = h0; th.y = h1;
    __nv_bfloat162 tl; tl.x = __float2bfloat16_rn(l0); tl.y = __float2bfloat16_rn(l1);
    hi = *(uint32_t*)&th;
    lo = *(uint32_t*)&tl;
}

// fast exp2 on FMA pipe (error ~2.4e-6)
__device__ __forceinline__ float fexp2(float x) {
    x = fmaxf(x, -120.f);
    int ni = __float2int_rn(x);
    float f = x - (float)ni;
    float p =          1.3333558146e-3f;
    p = fmaf(p, f, 9.6181291076e-3f);
    p = fmaf(p, f, 5.5504108664e-2f);
    p = fmaf(p, f, 2.4022650696e-1f);
    p = fmaf(p, f, 6.9314718056e-1f);
    p = fmaf(p, f, 1.0f);
    return __int_as_float((ni + 127) << 23) * p;
}

// ---------------------------------------------------------------------------
// bf16 hi/lo split of an fp32 buffer
// ---------------------------------------------------------------------------
__global__ __launch_bounds__(256)
void split_bf16_kernel(const float* __restrict__ in,
                       __nv_bfloat16* __restrict__ hi,
                       __nv_bfloat16* __restrict__ lo, int n2)
{
    int i = blockIdx.x * blockDim.x + threadIdx.x;
    if (i >= n2) return;
    float2 v = ((const float2*)in)[i];
    uint32_t h, l;
    split2(v.x, v.y, h, l);
    ((uint32_t*)hi)[i] = h;
    ((uint32_t*)lo)[i] = l;
}

// ---------------------------------------------------------------------------
// mma.sync bf16 split-GEMM (round-4 proven config): 3 passes (hh, lh, hl).
// CTA 128x128, BK=64, 256 thr = 8 warps (2m x 4n), warp tile 64x32.
// ---------------------------------------------------------------------------
#define KT_   (K_ / 64)
#define NIT_  (3 * KT_)
#define TILEB 16384
#define GEMM_SMEM (4 * TILEB + 128)

__device__ __forceinline__ void issue_tile_load(
    int L,
    const __nv_bfloat16* __restrict__ Ah, const __nv_bfloat16* __restrict__ Al,
    const __nv_bfloat16* __restrict__ Bh, const __nv_bfloat16* __restrict__ Bl,
    uint32_t sA, uint32_t sB, int m0, int n0, int tid)
{
    const int p  = L >> 4;
    const int kt = L & 15;
    const __nv_bfloat16* A = (p == 1) ? Al : Ah;
    const __nv_bfloat16* B = (p == 2) ? Bl : Bh;
    const int r0 = tid >> 3;
    const int ch = tid & 7;
    const uint32_t cb = (uint32_t)ch * 16u;
#pragma unroll
    for (int q = 0; q < 4; q++) {
        const int row = r0 + q * 32;
        const uint32_t sw = (uint32_t)row * 128u + (cb ^ (((uint32_t)row & 7u) << 4));
        CP_ASYNC_16(sA + sw, A + (size_t)(m0 + row) * K_ + kt * 64 + ch * 8);
        CP_ASYNC_16(sB + sw, B + (size_t)(n0 + row) * K_ + kt * 64 + ch * 8);
    }
    CP_ASYNC_COMMIT();
}

template<bool SPLIT_OUT>
__global__ __launch_bounds__(256)
void gemm_bf16_split_kernel(const __nv_bfloat16* __restrict__ Ah,
                            const __nv_bfloat16* __restrict__ Al,
                            const __nv_bfloat16* __restrict__ Bh,
                            const __nv_bfloat16* __restrict__ Bl,
                            float* __restrict__ Cm,
                            __nv_bfloat16* __restrict__ Oh,
                            __nv_bfloat16* __restrict__ Ol, int N)
{
    extern __shared__ char dsm[];
    const uint32_t base = (smem_u32(dsm) + 127u) & ~127u;

    const int tid  = threadIdx.x;
    const int wid  = tid >> 5;
    const int lane = tid & 31;
    const int wm   = wid >> 2;
    const int wn   = wid & 3;
    const int m0 = blockIdx.y * 128;
    const int n0 = blockIdx.x * 128;

    const uint32_t sA[2] = { base,         base + 2 * TILEB };
    const uint32_t sB[2] = { base + TILEB, base + 3 * TILEB };

    float acc[4][4][4];
#pragma unroll
    for (int i = 0; i < 4; i++)
#pragma unroll
        for (int j = 0; j < 4; j++)
#pragma unroll
            for (int q = 0; q < 4; q++) acc[i][j][q] = 0.f;

    const int lr = lane & 15;
    const uint32_t lc = ((uint32_t)(lane >> 4)) << 4;

    issue_tile_load(0, Ah, Al, Bh, Bl, sA[0], sB[0], m0, n0, tid);
    issue_tile_load(1, Ah, Al, Bh, Bl, sA[1], sB[1], m0, n0, tid);

    for (int it = 0; it < NIT_; ++it) {
        const int s = it & 1;
        if (it + 2 < NIT_) { CP_ASYNC_WAIT_1(); } else { CP_ASYNC_WAIT_0(); }
        __syncthreads();

#pragma unroll
        for (int kk = 0; kk < 4; kk++) {
            const uint32_t colb = (uint32_t)kk * 32u + lc;
            uint32_t a[4][4];
#pragma unroll
            for (int mi = 0; mi < 4; mi++) {
                const int row = wm * 64 + mi * 16 + lr;
                const uint32_t ad = sA[s] + (uint32_t)row * 128u +
                                    (colb ^ (((uint32_t)row & 7u) << 4));
                ldm_x4(a[mi][0], a[mi][1], a[mi][2], a[mi][3], ad);
            }
            uint32_t b[4][2];
#pragma unroll
            for (int bj = 0; bj < 2; bj++) {
                const int row = wn * 32 + bj * 16 + lr;
                const uint32_t ad = sB[s] + (uint32_t)row * 128u +
                                    (colb ^ (((uint32_t)row & 7u) << 4));
                uint32_t r0, r1, r2, r3;
                ldm_x4(r0, r1, r2, r3, ad);
                b[bj * 2 + 0][0] = r0; b[bj * 2 + 1][0] = r1;
                b[bj * 2 + 0][1] = r2; b[bj * 2 + 1][1] = r3;
            }
#pragma unroll
            for (int mi = 0; mi < 4; mi++)
#pragma unroll
                for (int ni = 0; ni < 4; ni++)
                    mma16816(acc[mi][ni], a[mi], b[ni]);
        }
        __syncthreads();

        if (it + 2 < NIT_)
            issue_tile_load(it + 2, Ah, Al, Bh, Bl, sA[s], sB[s], m0, n0, tid);
    }

    const int rr = lane >> 2;
    const int cc = (lane & 3) * 2;
#pragma unroll
    for (int mi = 0; mi < 4; mi++) {
#pragma unroll
        for (int ni = 0; ni < 4; ni++) {
            const int gm = m0 + wm * 64 + mi * 16 + rr;
            const int gn = n0 + wn * 32 + ni * 8 + cc;
            if (!SPLIT_OUT) {
                *(float2*)(Cm + (size_t)gm * N + gn) =
                    make_float2(acc[mi][ni][0], acc[mi][ni][1]);
                *(float2*)(Cm + (size_t)(gm + 8) * N + gn) =
                    make_float2(acc[mi][ni][2], acc[mi][ni][3]);
            } else {
                uint32_t h, l;
                split2(acc[mi][ni][0], acc[mi][ni][1], h, l);
                *(uint32_t*)(Oh + (size_t)gm * N + gn) = h;
                *(uint32_t*)(Ol + (size_t)gm * N + gn) = l;
                split2(acc[mi][ni][2], acc[mi][ni][3], h, l);
                *(uint32_t*)(Oh + (size_t)(gm + 8) * N + gn) = h;
                *(uint32_t*)(Ol + (size_t)(gm + 8) * N + gn) = l;
            }
        }
    }
}

// ---------------------------------------------------------------------------
// Tensor-core flash attention (causal), bf16 hi/lo, poly-exp2 softmax.
// V kept in natural [kv][d] layout; P@V B-fragments via ldmatrix.x4.trans
// -> no smem transpose, ONE __syncthreads per KV tile.
// CTA: 256 thr = 8 warps, BQ=128, BKV=64, D=64.
// ---------------------------------------------------------------------------
#define BQ_   128
#define BKV_  64
#define AQH   0u
#define AQL   16384u
#define AKST  32768u      // + s*16384 : Kh +0, Kl +8192
#define AVST  65536u      // + s*16384 : Vh +0, Vl +8192
#define ATTN_SMEM (98304 + 1024)

__global__ __launch_bounds__(256, 1)
void attn_mma_kernel(const __nv_bfloat16* __restrict__ qh_g,
                     const __nv_bfloat16* __restrict__ ql_g,
                     __nv_bfloat16* __restrict__ oh_g,
                     __nv_bfloat16* __restrict__ ol_g)
{
    extern __shared__ char dsm[];
    char* sm = (char*)(((uintptr_t)dsm + 1023) & ~(uintptr_t)1023);
    const uint32_t smb = smem_u32(sm);

    const int qb = (int)gridDim.x - 1 - (int)blockIdx.x;  // big work first
    const int h  = blockIdx.y, b = blockIdx.z;
    const int q0 = qb * BQ_;
    const int tid  = threadIdx.x;
    const int w    = tid >> 5;
    const int lane = tid & 31;
    const int lr   = lane & 15;
    const uint32_t lc = ((uint32_t)(lane >> 4)) << 4;
    const float SC = 0.18033688011f;   // (1/8) * log2(e)

    // ---- prologue: Q tile (hi+lo) ----
    {
        const int r  = tid >> 1;
        const int cb = (tid & 1) * 4;
        const size_t grow = (size_t)(b * T_ + q0 + r) * QKVN + h * D_;
#pragma unroll
        for (int c = 0; c < 4; c++) {
            const uint32_t off = (uint32_t)r * 128u +
                (((uint32_t)(cb + c) * 16u) ^ (((uint32_t)r & 7u) << 4));
            CP_ASYNC_16(smb + AQH + off, qh_g + grow + (cb + c) * 8);
            CP_ASYNC_16(smb + AQL + off, ql_g + grow + (cb + c) * 8);
        }
        CP_ASYNC_COMMIT();
    }

    // KV tile loader: K and V (natural layout), hi+lo, stage s
    auto issue_kv = [&](int kt, int s) {
        const int r  = tid >> 2;          // 0..63
        const int c0 = tid & 3;
        const size_t krow = (size_t)(b * T_ + kt * BKV_ + r) * QKVN + C_     + h * D_;
        const size_t vrow = (size_t)(b * T_ + kt * BKV_ + r) * QKVN + 2 * C_ + h * D_;
        const uint32_t ks = smb + AKST + (uint32_t)s * 16384u;
        const uint32_t vs = smb + AVST + (uint32_t)s * 16384u;
        const uint32_t rx = ((uint32_t)r & 7u) << 4;
#pragma unroll
        for (int q = 0; q < 2; q++) {
            const int c = c0 + q * 4;
            const uint32_t off = (uint32_t)r * 128u + (((uint32_t)c * 16u) ^ rx);
            CP_ASYNC_16(ks + off,         qh_g + krow + c * 8);
            CP_ASYNC_16(ks + 8192u + off, ql_g + krow + c * 8);
            CP_ASYNC_16(vs + off,         qh_g + vrow + c * 8);
            CP_ASYNC_16(vs + 8192u + off, ql_g + vrow + c * 8);
        }
        CP_ASYNC_COMMIT();
    };

    issue_kv(0, 0);
    CP_ASYNC_WAIT_1();      // Q group done
    __syncthreads();

    // ---- Q fragments into registers ----
    uint32_t qhf[4][4], qlf[4][4];
#pragma unroll
    for (int kk = 0; kk < 4; kk++) {
        const int row = w * 16 + lr;
        const uint32_t colb = (uint32_t)kk * 32u + lc;
        const uint32_t sw = (uint32_t)row * 128u +
                            (colb ^ (((uint32_t)row & 7u) << 4));
        ldm_x4(qhf[kk][0], qhf[kk][1], qhf[kk][2], qhf[kk][3], smb + AQH + sw);
        ldm_x4(qlf[kk][0], qlf[kk][1], qlf[kk][2], qlf[kk][3], smb + AQL + sw);
    }

    float acco[8][4];
#pragma unroll
    for (int j = 0; j < 8; j++)
#pragma unroll
        for (int q = 0; q < 4; q++) acco[j][q] = 0.f;
    float m_[2] = { -1e30f, -1e30f };
    float l_[2] = { 0.f, 0.f };

    const int nkb = 2 * qb + 2;
    for (int kt = 0; kt < nkb; kt++) {
        const int s  = kt & 1;
        const int k0 = kt * BKV_;
        CP_ASYNC_WAIT_0();
        __syncthreads();                 // single barrier per tile
        if (kt + 1 < nkb) issue_kv(kt + 1, s ^ 1);

        const uint32_t ks = smb + AKST + (uint32_t)s * 16384u;
        const uint32_t vs = smb + AVST + (uint32_t)s * 16384u;

        // ---- S = Q @ K^T (3-pass split) ----
        float accs[8][4];
#pragma unroll
        for (int j = 0; j < 8; j++)
#pragma unroll
            for (int q = 0; q < 4; q++) accs[j][q] = 0.f;

#pragma unroll
        for (int kk = 0; kk < 4; kk++) {
            uint32_t bh[8][2], bl[8][2];
#pragma unroll
            for (int bj = 0; bj < 4; bj++) {
                const int row = bj * 16 + lr;
                const uint32_t colb = (uint32_t)kk * 32u + lc;
                const uint32_t ad = ks + (uint32_t)row * 128u +
                                    (colb ^ (((uint32_t)row & 7u) << 4));
                uint32_t r0, r1, r2, r3;
                ldm_x4(r0, r1, r2, r3, ad);
                bh[bj*2][0]=r0; bh[bj*2+1][0]=r1; bh[bj*2][1]=r2; bh[bj*2+1][1]=r3;
                ldm_x4(r0, r1, r2, r3, ad + 8192u);
                bl[bj*2][0]=r0; bl[bj*2+1][0]=r1; bl[bj*2][1]=r2; bl[bj*2+1][1]=r3;
            }
#pragma unroll
            for (int j = 0; j < 8; j++) {
                mma16816(accs[j], qhf[kk], bh[j]);
                mma16816(accs[j], qlf[kk], bh[j]);
                mma16816(accs[j], qhf[kk], bl[j]);
            }
        }

        // ---- causal mask + online softmax ----
        const int qg_base = q0 + w * 16 + (lane >> 2);
        const bool full = (k0 + BKV_ - 1) <= (q0 + w * 16);  // warp-uniform
#pragma unroll
        for (int pp = 0; pp < 2; pp++) {
            const int qg = qg_base + 8 * pp;
            float mx = m_[pp];
            if (full) {
#pragma unroll
                for (int j = 0; j < 8; j++) {
                    float v0 = accs[j][2*pp  ] * SC;
                    float v1 = accs[j][2*pp+1] * SC;
                    accs[j][2*pp] = v0; accs[j][2*pp+1] = v1;
                    mx = fmaxf(mx, fmaxf(v0, v1));
                }
            } else {
#pragma unroll
                for (int j = 0; j < 8; j++) {
                    const int kg = k0 + j * 8 + (lane & 3) * 2;
                    float v0 = (kg     <= qg) ? accs[j][2*pp  ] * SC : -1e30f;
                    float v1 = (kg + 1 <= qg) ? accs[j][2*pp+1] * SC : -1e30f;
                    accs[j][2*pp] = v0; accs[j][2*pp+1] = v1;
                    mx = fmaxf(mx, fmaxf(v0, v1));
                }
            }
            mx = fmaxf(mx, __shfl_xor_sync(0xffffffffu, mx, 1));
            mx = fmaxf(mx, __shfl_xor_sync(0xffffffffu, mx, 2));
            const float alpha = fexp2(m_[pp] - mx);
            float rs = 0.f;
#pragma unroll
            for (int j = 0; j < 8; j++) {
                const float p0 = fexp2(accs[j][2*pp  ] - mx);
                const float p1 = fexp2(accs[j][2*pp+1] - mx);
                accs[j][2*pp] = p0; accs[j][2*pp+1] = p1;
                rs += p0 + p1;
            }
            rs += __shfl_xor_sync(0xffffffffu, rs, 1);
            rs += __shfl_xor_sync(0xffffffffu, rs, 2);
            l_[pp] = l_[pp] * alpha + rs;
            m_[pp] = mx;
#pragma unroll
            for (int j = 0; j < 8; j++) {
                acco[j][2*pp] *= alpha; acco[j][2*pp+1] *= alpha;
            }
        }

        // ---- pack P (hi/lo) into A fragments ----
        uint32_t ph[4][4], pl[4][4];
#pragma unroll
        for (int t = 0; t < 4; t++) {
            split2(accs[2*t  ][0], accs[2*t  ][1], ph[t][0], pl[t][0]);
            split2(accs[2*t  ][2], accs[2*t  ][3], ph[t][1], pl[t][1]);
            split2(accs[2*t+1][0], accs[2*t+1][1], ph[t][2], pl[t][2]);
            split2(accs[2*t+1][2], accs[2*t+1][3], ph[t][3], pl[t][3]);
        }

        // ---- O += P @ V (3-pass split); B frags from natural V via trans ----
        const int li  = lane & 7;
        const int sel = lane >> 3;
#pragma unroll
        for (int kk = 0; kk < 4; kk++) {
            uint32_t bvh[8][2], bvl[8][2];
#pragma unroll
            for (int dj = 0; dj < 4; dj++) {
                // x4.trans: m0=(kv 0-7, d0-7), m1=(kv 8-15, d0-7),
                //           m2=(kv 0-7, d8-15), m3=(kv 8-15, d8-15)
                const int row = kk * 16 + li + (sel & 1) * 8;
                const uint32_t colb = (uint32_t)dj * 32u + ((uint32_t)(sel >> 1) << 4);
                const uint32_t ad = vs + (uint32_t)row * 128u +
                                    (colb ^ (((uint32_t)row & 7u) << 4));
                uint32_t r0, r1, r2, r3;
                ldm_x4_trans(r0, r1, r2, r3, ad);
                bvh[dj*2  ][0] = r0; bvh[dj*2  ][1] = r1;
                bvh[dj*2+1][0] = r2; bvh[dj*2+1][1] = r3;
                ldm_x4_trans(r0, r1, r2, r3, ad + 8192u);
                bvl[dj*2  ][0] = r0; bvl[dj*2  ][1] = r1;
                bvl[dj*2+1][0] = r2; bvl[dj*2+1][1] = r3;
            }
#pragma unroll
            for (int j = 0; j < 8; j++) {
                mma16816(acco[j], ph[kk], bvh[j]);
                mma16816(acco[j], pl[kk], bvh[j]);
                mma16816(acco[j], ph[kk], bvl[j]);
            }
        }
    }

    // ---- epilogue: normalize, split, write [B*T, C] ----
#pragma unroll
    for (int pp = 0; pp < 2; pp++) {
        const float inv = 1.f / l_[pp];
        const size_t row = (size_t)(b * T_ + q0 + w * 16 + (lane >> 2) + 8 * pp);
#pragma unroll
        for (int j = 0; j < 8; j++) {
            const int dcol = h * D_ + j * 8 + (lane & 3) * 2;
            uint32_t hbits, lbits;
            split2(acco[j][2*pp] * inv, acco[j][2*pp+1] * inv, hbits, lbits);
            *(uint32_t*)(oh_g + row * C_ + dcol) = hbits;
            *(uint32_t*)(ol_g + row * C_ + dcol) = lbits;
        }
    }
}

// ---------------------------------------------------------------------------
extern "C" void kernel_launch(void* const* d_in, const int* in_sizes, int n_in,
                              void* d_out, int out_size)
{
    (void)in_sizes; (void)n_in; (void)out_size;
    const float* x     = (const float*)d_in[0];
    const float* wqkv  = (const float*)d_in[1];
    const float* wproj = (const float*)d_in[2];
    float* out = (float*)d_out;

    __nv_bfloat16 *xh, *xl, *wqh, *wql, *qkvh, *qkvl, *ah, *al, *wph, *wpl;
    cudaGetSymbolAddress((void**)&xh,   s_xh);
    cudaGetSymbolAddress((void**)&xl,   s_xl);
    cudaGetSymbolAddress((void**)&wqh,  s_wqh);
    cudaGetSymbolAddress((void**)&wql,  s_wql);
    cudaGetSymbolAddress((void**)&qkvh, s_qkvh);
    cudaGetSymbolAddress((void**)&qkvl, s_qkvl);
    cudaGetSymbolAddress((void**)&ah,   s_ah);
    cudaGetSymbolAddress((void**)&al,   s_al);
    cudaGetSymbolAddress((void**)&wph,  s_wph);
    cudaGetSymbolAddress((void**)&wpl,  s_wpl);

    cudaFuncSetAttribute(gemm_bf16_split_kernel<true>,
                         cudaFuncAttributeMaxDynamicSharedMemorySize, GEMM_SMEM);
    cudaFuncSetAttribute(gemm_bf16_split_kernel<false>,
                         cudaFuncAttributeMaxDynamicSharedMemorySize, GEMM_SMEM);
    cudaFuncSetAttribute(attn_mma_kernel,
                         cudaFuncAttributeMaxDynamicSharedMemorySize, ATTN_SMEM);

    // 1) split inputs
    {
        int n2 = (M_ * C_) / 2;
        split_bf16_kernel<<<(n2 + 255) / 256, 256>>>(x, xh, xl, n2);
        int w2 = (QKVN * C_) / 2;
        split_bf16_kernel<<<(w2 + 255) / 256, 256>>>(wqkv, wqh, wql, w2);
        int p2 = (C_ * C_) / 2;
        split_bf16_kernel<<<(p2 + 255) / 256, 256>>>(wproj, wph, wpl, p2);
    }
    // 2) QKV projection -> bf16 hi/lo
    gemm_bf16_split_kernel<true><<<dim3(QKVN / 128, M_ / 128), 256, GEMM_SMEM>>>(
        xh, xl, wqh, wql, nullptr, qkvh, qkvl, QKVN);
    // 3) causal flash attention (tensor cores, trans-V)
    attn_mma_kernel<<<dim3(T_ / BQ_, H_, B_), 256, ATTN_SMEM>>>(
        qkvh, qkvl, ah, al);
    // 4) output projection -> fp32
    gemm_bf16_split_kernel<false><<<dim3(C_ / 128, M_ / 128), 256, GEMM_SMEM>>>(
        ah, al, wph, wpl, out, nullptr, nullptr, C_);
}